// round 10
// baseline (speedup 1.0000x reference)
#include <cuda_runtime.h>
#include <cuda_bf16.h>
#include <math.h>

// ---------------- problem constants ----------------
#define VOCAB 50257
#define EMBD  32
#define HID   8
#define NB    48     // batch
#define NT    128    // seq
#define NROWS (NB*NT)          // 6144
#define VP    51200            // padded vocab width (200 chunks of 256)
#define NCH2  200              // chunks of 256 cols
#define VS    8                // vocab splits
#define CPC   (NCH2/VS)        // 25 chunks per CTA

// ---------------- device scratch (no cudaMalloc allowed) ----------------
__device__ __align__(16) float g_W4[4 * 16 * VP];   // 4 shifted copies of h2o, padded
__device__ __align__(16) float g_Bs[NB * VP];       // per-b shifted bias, padded with -1e30
__device__ __align__(16) float g_E [NB * NT * HID]; // E[b][t][j] = emb @ i2h[:32]
__device__ __align__(16) float g_H [NB * NT * 16];  // H[b][t][0:8]=hf_used, [8:16]=hb_used
__device__ float g_Zpart[NROWS * VS];
__device__ float g_LZ  [NROWS];

typedef unsigned long long u64;

// ---------------- f32x2 helpers (sm_103a packed fp32) ----------------
__device__ __forceinline__ u64 pk2(float x) {
    u64 r; asm("mov.b64 %0,{%1,%1};" : "=l"(r) : "f"(x)); return r;
}
__device__ __forceinline__ u64 f2fma(u64 a, u64 b, u64 c) {
    u64 d; asm("fma.rn.f32x2 %0,%1,%2,%3;" : "=l"(d) : "l"(a), "l"(b), "l"(c)); return d;
}
__device__ __forceinline__ u64 f2add(u64 a, u64 b) {
    u64 d; asm("add.rn.f32x2 %0,%1,%2;" : "=l"(d) : "l"(a), "l"(b)); return d;
}
__device__ __forceinline__ float2 up2(u64 a) {
    float2 f; asm("mov.b64 {%0,%1},%2;" : "=f"(f.x), "=f"(f.y) : "l"(a)); return f;
}
__device__ __forceinline__ void cp16(void* dst, const void* src) {
    unsigned saddr = (unsigned)__cvta_generic_to_shared(dst);
    asm volatile("cp.async.cg.shared.global [%0], [%1], 16;" :: "r"(saddr), "l"(src));
}

// ---------------- fused prep: shifted/padded W copies + shifted bias ----------------
#define W_TOTAL (4 * 16 * VP)
#define B_TOTAL (NB * VP)
__global__ void prep_kernel(const float* __restrict__ h2o,
                            const float* __restrict__ bias) {
    int idx = blockIdx.x * blockDim.x + threadIdx.x;
    if (idx < W_TOTAL) {
        int s = idx / (16 * VP);
        int rem = idx - s * (16 * VP);
        int k = rem / VP;
        int i = rem - k * VP;
        int lo = i - s;
        float v = 0.0f;
        if (lo >= 0 && lo < VOCAB) v = h2o[k * VOCAB + lo];
        g_W4[idx] = v;
    } else {
        int j = idx - W_TOTAL;
        if (j >= B_TOTAL) return;
        int b = j / VP;
        int i = j - b * VP;
        int s = b & 3;
        int lo = i - s;
        float v = -1e30f;
        if (lo >= 0 && lo < VOCAB) v = bias[b * VOCAB + lo];
        g_Bs[j] = v;
    }
}

// ---------------- E = gather(we, ids) @ i2h[0:32,:] ----------------
__global__ void emb_kernel(const int* __restrict__ ids,
                           const float* __restrict__ we,
                           const float* __restrict__ i2h) {
    int gid = blockIdx.x * blockDim.x + threadIdx.x;
    if (gid >= NROWS * HID) return;
    int r = gid >> 3;
    int j = gid & 7;
    int t = r / NB;
    int b = r - t * NB;
    int id = ids[r];
    const float* wr = we + (long)id * EMBD;
    float acc = 0.0f;
#pragma unroll
    for (int k = 0; k < EMBD; k++)
        acc += __ldg(wr + k) * __ldg(i2h + k * HID + j);
    g_E[((b << 7) + t) * HID + j] = acc;
}

// ---------------- RNN scans: 96 warps (48 b x 2 dir), fast tanh ----------------
__global__ void rnn_kernel(const float* __restrict__ i2h,
                           const float* __restrict__ h0f,
                           const float* __restrict__ h0b) {
    int wg = blockIdx.x * (blockDim.x >> 5) + (threadIdx.x >> 5);
    if (wg >= 2 * NB) return;
    int lane = threadIdx.x & 31;
    int j = lane & 7;
    int dir = (wg >= NB) ? 1 : 0;
    int b = wg - dir * NB;

    float U[HID];
#pragma unroll
    for (int kk = 0; kk < HID; kk++)
        U[kk] = i2h[(EMBD + kk) * HID + j];

    float h = dir ? h0b[b * HID + j] : h0f[b * HID + j];

    int t_first = dir ? (NT - 1) : 0;
    float e_cur = g_E[((b << 7) + t_first) * HID + j];

    for (int step = 0; step < NT; step++) {
        int t = dir ? (NT - 1 - step) : step;
        float e_next = 0.0f;
        if (step + 1 < NT) {
            int tn = dir ? (NT - 2 - step) : (step + 1);
            e_next = g_E[((b << 7) + tn) * HID + j];
        }
        if (lane < HID)
            g_H[((b << 7) + t) * 16 + dir * HID + j] = h;
        float acc = e_cur;
#pragma unroll
        for (int kk = 0; kk < HID; kk++)
            acc += __shfl_sync(0xFFFFFFFFu, h, kk) * U[kk];
        float ex = __expf(2.0f * acc);
        h = (ex - 1.0f) * __fdividef(1.0f, ex + 1.0f);
        e_cur = e_next;
    }
}

// ---------------- main passes ----------------
// grid: 48 b * 2 t-tiles * 8 vs = 768 CTAs, 256 threads, occ 2.
// 256-col chunks streamed gmem -> smem (triple-buffered cp.async, 2 ahead).
// Warp owns 8 rows; lane owns 8 cols/chunk (C=8).
// L1wf/fma = 4/R + 2/C = 0.75 -> fma-bound. kg loop FORCED ROLLED so W
// staging stays at 16 u64: acc 64 regs + W 32 + misc ~= 122 < 128 cap.
template<int PASS>
__global__ __launch_bounds__(256, 2) void pass_kernel(float* __restrict__ out) {
    int bx = blockIdx.x;
    int vs = bx & (VS - 1);
    int tmp = bx >> 3;
    int tt = tmp & 1;
    int b = tmp >> 1;
    int t0 = tt << 6;
    int s = b & 3;

    const float* __restrict__ W  = g_W4 + s * (16 * VP);
    const float* __restrict__ Bp = g_Bs + b * VP;

    __shared__ __align__(16) float smw[3][16 * 256];  // 3 x 16KB W chunk buffers
    __shared__ __align__(16) u64 smh[64 * 16];        // (h,h) packed per row,k
    __shared__ u64 smlz[64];                          // (-lz,-lz) packed

    int tid = threadIdx.x;

    // prefetch of one 256-col W chunk: 1024 float4; each thread copies 4
    auto prefetch = [&](int ci, int buf) {
        int colbase = ((ci << 3) + vs) << 8;
        const float* src = W + colbase;
#pragma unroll
        for (int h = 0; h < 4; h++) {
            int f4 = tid + h * 256;          // 0..1023
            int k = f4 >> 6;                 // 64 float4 per k-row
            int c = (f4 & 63) << 2;
            cp16(&smw[buf][k * 256 + c], src + (long)k * VP + c);
        }
        asm volatile("cp.async.commit_group;" ::: "memory");
    };

    prefetch(0, 0);
    prefetch(1, 1);

    for (int i = tid; i < 1024; i += 256)
        smh[i] = pk2(g_H[(((b << 7) + t0) << 4) + i]);
    if (PASS == 2 && tid < 64)
        smlz[tid] = pk2(-g_LZ[(b << 7) + t0 + tid]);

    int warp = tid >> 5, lane = tid & 31;
    int r0 = warp << 3;                               // 8 rows per warp
    float zz[8];
#pragma unroll
    for (int r = 0; r < 8; r++) zz[r] = 0.0f;

    for (int ci = 0; ci < CPC; ci++) {
        int p = ci % 3;
        if (ci < CPC - 1) asm volatile("cp.async.wait_group 1;" ::: "memory");
        else              asm volatile("cp.async.wait_group 0;" ::: "memory");
        __syncthreads();   // chunk ci landed for all threads (covers smh on ci==0)

        int col = (((ci << 3) + vs) << 8) + (lane << 3);
        u64 a[8][4];
        {
            ulonglong2 bb0 = *(const ulonglong2*)(Bp + col);
            ulonglong2 bb1 = *(const ulonglong2*)(Bp + col + 4);
#pragma unroll
            for (int r = 0; r < 8; r++) {
                a[r][0] = bb0.x; a[r][1] = bb0.y;
                a[r][2] = bb1.x; a[r][3] = bb1.y;
            }
        }

        const float* wl = &smw[p][lane << 3];
#pragma unroll 1
        for (int kg = 0; kg < 4; kg++) {
            const float* wp = wl + (kg << 10);        // kg*4 k-rows * 256
            ulonglong2 w00 = *(const ulonglong2*)(wp);
            ulonglong2 w01 = *(const ulonglong2*)(wp + 4);
            ulonglong2 w10 = *(const ulonglong2*)(wp + 256);
            ulonglong2 w11 = *(const ulonglong2*)(wp + 260);
            ulonglong2 w20 = *(const ulonglong2*)(wp + 512);
            ulonglong2 w21 = *(const ulonglong2*)(wp + 516);
            ulonglong2 w30 = *(const ulonglong2*)(wp + 768);
            ulonglong2 w31 = *(const ulonglong2*)(wp + 772);
#pragma unroll
            for (int r = 0; r < 8; r++) {
                const ulonglong2* hp = (const ulonglong2*)&smh[((r0 + r) << 4) + (kg << 2)];
                ulonglong2 h01 = hp[0];
                ulonglong2 h23 = hp[1];
                a[r][0] = f2fma(h01.x, w00.x, a[r][0]);
                a[r][1] = f2fma(h01.x, w00.y, a[r][1]);
                a[r][2] = f2fma(h01.x, w01.x, a[r][2]);
                a[r][3] = f2fma(h01.x, w01.y, a[r][3]);
                a[r][0] = f2fma(h01.y, w10.x, a[r][0]);
                a[r][1] = f2fma(h01.y, w10.y, a[r][1]);
                a[r][2] = f2fma(h01.y, w11.x, a[r][2]);
                a[r][3] = f2fma(h01.y, w11.y, a[r][3]);
                a[r][0] = f2fma(h23.x, w20.x, a[r][0]);
                a[r][1] = f2fma(h23.x, w20.y, a[r][1]);
                a[r][2] = f2fma(h23.x, w21.x, a[r][2]);
                a[r][3] = f2fma(h23.x, w21.y, a[r][3]);
                a[r][0] = f2fma(h23.y, w30.x, a[r][0]);
                a[r][1] = f2fma(h23.y, w30.y, a[r][1]);
                a[r][2] = f2fma(h23.y, w31.x, a[r][2]);
                a[r][3] = f2fma(h23.y, w31.y, a[r][3]);
            }
        }

#pragma unroll
        for (int r = 0; r < 8; r++) {
            if (PASS == 1) {
                float2 p0 = up2(a[r][0]), p1 = up2(a[r][1]);
                float2 p2 = up2(a[r][2]), p3 = up2(a[r][3]);
                zz[r] += ((__expf(p0.x) + __expf(p0.y)) + (__expf(p1.x) + __expf(p1.y)))
                       + ((__expf(p2.x) + __expf(p2.y)) + (__expf(p3.x) + __expf(p3.y)));
            } else {
                int row = r0 + r;
                u64 lz = smlz[row];
                u64 a0 = f2add(a[r][0], lz);
                u64 a1 = f2add(a[r][1], lz);
                u64 a2 = f2add(a[r][2], lz);
                u64 a3 = f2add(a[r][3], lz);
                long rowbase = (long)((t0 + row) * NB + b) * VOCAB;
                int lo = col - s;
                float2 p0 = up2(a0), p1 = up2(a1), p2 = up2(a2), p3 = up2(a3);
                if (lo >= 0 && lo + 8 <= VOCAB) {
                    // rowbase % 4 == s, lo % 4 == (4-s)%4 -> 16B-aligned stores
                    __stcs((float4*)(out + rowbase + lo),
                           make_float4(p0.x, p0.y, p1.x, p1.y));
                    __stcs((float4*)(out + rowbase + lo + 4),
                           make_float4(p2.x, p2.y, p3.x, p3.y));
                } else {
                    float vals[8] = {p0.x, p0.y, p1.x, p1.y, p2.x, p2.y, p3.x, p3.y};
#pragma unroll
                    for (int e = 0; e < 8; e++) {
                        int v = lo + e;
                        if (v >= 0 && v < VOCAB) __stcs(out + rowbase + v, vals[e]);
                    }
                }
            }
        }

        if (ci + 2 < CPC) prefetch(ci + 2, (ci + 2) % 3);
    }

    if (PASS == 1) {
#pragma unroll
        for (int r = 0; r < 8; r++) {
            float zr = zz[r];
#pragma unroll
            for (int o = 16; o; o >>= 1) zr += __shfl_xor_sync(0xFFFFFFFFu, zr, o);
            if (lane == 0)
                g_Zpart[((b << 7) + t0 + r0 + r) * VS + vs] = zr;
        }
    }
}

// ---------------- reduce Z partials -> logZ ----------------
__global__ void reduce_kernel() {
    int r = blockIdx.x * blockDim.x + threadIdx.x;
    if (r >= NROWS) return;
    float ssum = 0.0f;
#pragma unroll
    for (int v = 0; v < VS; v++) ssum += g_Zpart[r * VS + v];
    g_LZ[r] = logf(ssum);
}

// ---------------- launch ----------------
extern "C" void kernel_launch(void* const* d_in, const int* in_sizes, int n_in,
                              void* d_out, int out_size) {
    const int*   ids  = (const int*)  d_in[0];
    const float* we   = (const float*)d_in[1];
    const float* i2h  = (const float*)d_in[2];
    const float* h2o  = (const float*)d_in[3];
    const float* bias = (const float*)d_in[4];
    const float* h0f  = (const float*)d_in[5];
    const float* h0b  = (const float*)d_in[6];
    float* out = (float*)d_out;

    {
        int n = W_TOTAL + B_TOTAL;
        prep_kernel<<<(n + 255) / 256, 256>>>(h2o, bias);       // launch 0
    }
    {
        int n = NROWS * HID;
        emb_kernel<<<(n + 255) / 256, 256>>>(ids, we, i2h);     // launch 1
    }
    rnn_kernel<<<24, 128>>>(i2h, h0f, h0b);                     // launch 2

    pass_kernel<1><<<NB * 2 * VS, 256>>>(out);                  // launch 3 (ncu capture slot)
    reduce_kernel<<<(NROWS + 255) / 256, 256>>>();              // launch 4
    pass_kernel<2><<<NB * 2 * VS, 256>>>(out);                  // launch 5
}

// round 14
// speedup vs baseline: 1.2764x; 1.2764x over previous
#include <cuda_runtime.h>
#include <cuda_bf16.h>
#include <math.h>

// ---------------- problem constants ----------------
#define VOCAB 50257
#define EMBD  32
#define HID   8
#define NB    48     // batch
#define NT    128    // seq
#define NROWS (NB*NT)          // 6144
#define VP    51200            // padded vocab width (400 chunks of 128)
#define VS    16               // vocab splits
#define NCH   400              // chunks of 128 cols
#define CPC   (NCH/VS)         // 25 chunks per CTA

#define LOG2E 1.4426950408889634f
#define LN2   0.6931471805599453f

// ---------------- device scratch (no cudaMalloc allowed) ----------------
__device__ __align__(16) float g_W4[4 * 16 * VP];   // 4 shifted copies of log2e*h2o, padded 0
__device__ __align__(16) float g_Bs[NB * VP];       // per-b shifted log2e*bias, pad -1e30
__device__ __align__(16) float g_E [NB * NT * HID]; // E[b][t][j] = emb @ i2h[:32]
__device__ __align__(16) float g_H [NB * NT * 16];  // H[b][t][0:8]=hf_used, [8:16]=hb_used
__device__ float g_Zpart[NROWS * VS];

typedef unsigned long long u64;

// ---------------- f32x2 helpers (sm_103a packed fp32) ----------------
__device__ __forceinline__ u64 pk2(float x) {
    u64 r; asm("mov.b64 %0,{%1,%1};" : "=l"(r) : "f"(x)); return r;
}
__device__ __forceinline__ u64 f2fma(u64 a, u64 b, u64 c) {
    u64 d; asm("fma.rn.f32x2 %0,%1,%2,%3;" : "=l"(d) : "l"(a), "l"(b), "l"(c)); return d;
}
__device__ __forceinline__ float2 up2(u64 a) {
    float2 f; asm("mov.b64 {%0,%1},%2;" : "=f"(f.x), "=f"(f.y) : "l"(a)); return f;
}
__device__ __forceinline__ float ex2f(float x) {
    float r; asm("ex2.approx.f32 %0, %1;" : "=f"(r) : "f"(x)); return r;
}
__device__ __forceinline__ void cp16(void* dst, const void* src) {
    unsigned saddr = (unsigned)__cvta_generic_to_shared(dst);
    asm volatile("cp.async.cg.shared.global [%0], [%1], 16;" :: "r"(saddr), "l"(src));
}

// ---------------- fused prep: shifted/padded log2e*W copies + log2e*bias ----------------
#define W_TOTAL (4 * 16 * VP)
#define B_TOTAL (NB * VP)
__global__ void prep_kernel(const float* __restrict__ h2o,
                            const float* __restrict__ bias) {
    int idx = blockIdx.x * blockDim.x + threadIdx.x;
    if (idx < W_TOTAL) {
        int s = idx / (16 * VP);
        int rem = idx - s * (16 * VP);
        int k = rem / VP;
        int i = rem - k * VP;
        int lo = i - s;
        float v = 0.0f;
        if (lo >= 0 && lo < VOCAB) v = LOG2E * h2o[k * VOCAB + lo];
        g_W4[idx] = v;
    } else {
        int j = idx - W_TOTAL;
        if (j >= B_TOTAL) return;
        int b = j / VP;
        int i = j - b * VP;
        int s = b & 3;
        int lo = i - s;
        float v = -1e30f;                 // ex2 -> 0 on pads
        if (lo >= 0 && lo < VOCAB) v = LOG2E * bias[b * VOCAB + lo];
        g_Bs[j] = v;
    }
}

// ---------------- E = gather(we, ids) @ i2h[0:32,:] ----------------
__global__ void emb_kernel(const int* __restrict__ ids,
                           const float* __restrict__ we,
                           const float* __restrict__ i2h) {
    int gid = blockIdx.x * blockDim.x + threadIdx.x;
    if (gid >= NROWS * HID) return;
    int r = gid >> 3;
    int j = gid & 7;
    int t = r / NB;
    int b = r - t * NB;
    int id = ids[r];
    const float* wr = we + (long)id * EMBD;
    float acc = 0.0f;
#pragma unroll
    for (int k = 0; k < EMBD; k++)
        acc += __ldg(wr + k) * __ldg(i2h + k * HID + j);
    g_E[((b << 7) + t) * HID + j] = acc;
}

// ---------------- RNN scans: 96 warps (48 b x 2 dir), tree-sum step ----------------
__global__ void rnn_kernel(const float* __restrict__ i2h,
                           const float* __restrict__ h0f,
                           const float* __restrict__ h0b) {
    int wg = blockIdx.x * (blockDim.x >> 5) + (threadIdx.x >> 5);
    if (wg >= 2 * NB) return;
    int lane = threadIdx.x & 31;
    int j = lane & 7;
    int dir = (wg >= NB) ? 1 : 0;
    int b = wg - dir * NB;

    float U[HID];
#pragma unroll
    for (int kk = 0; kk < HID; kk++)
        U[kk] = i2h[(EMBD + kk) * HID + j];

    float h = dir ? h0b[b * HID + j] : h0f[b * HID + j];
    int t_first = dir ? (NT - 1) : 0;
    float e_cur = g_E[((b << 7) + t_first) * HID + j];

    for (int step = 0; step < NT; step++) {
        int t = dir ? (NT - 1 - step) : step;
        float e_next = 0.0f;
        if (step + 1 < NT) {
            int tn = dir ? (NT - 2 - step) : (step + 1);
            e_next = g_E[((b << 7) + tn) * HID + j];
        }
        if (lane < HID)
            g_H[((b << 7) + t) * 16 + dir * HID + j] = h;
        // 8 independent products (shuffles issue back-to-back) + tree add
        float p0 = __shfl_sync(0xFFFFFFFFu, h, 0) * U[0];
        float p1 = __shfl_sync(0xFFFFFFFFu, h, 1) * U[1];
        float p2 = __shfl_sync(0xFFFFFFFFu, h, 2) * U[2];
        float p3 = __shfl_sync(0xFFFFFFFFu, h, 3) * U[3];
        float p4 = __shfl_sync(0xFFFFFFFFu, h, 4) * U[4];
        float p5 = __shfl_sync(0xFFFFFFFFu, h, 5) * U[5];
        float p6 = __shfl_sync(0xFFFFFFFFu, h, 6) * U[6];
        float p7 = __shfl_sync(0xFFFFFFFFu, h, 7) * U[7];
        float acc = (((p0 + p1) + (p2 + p3)) + ((p4 + p5) + (p6 + p7))) + e_cur;
        float ex = __expf(2.0f * acc);
        h = (ex - 1.0f) * __fdividef(1.0f, ex + 1.0f);
        e_cur = e_next;
    }
}

// ---------------- main passes ----------------
// grid: 48 b * 2 t-tiles * 16 vs = 1536 CTAs, 256 threads, occ 2. (R8-proven)
// W streamed gmem -> smem (triple-buffered cp.async, 2 chunks ahead).
// Warp owns 8 rows; lane owns 4 cols/chunk. Accumulators in log2 units.
template<int PASS>
__global__ __launch_bounds__(256, 2) void pass_kernel(float* __restrict__ out) {
    int bx = blockIdx.x;
    int vs = bx & (VS - 1);
    int tmp = bx >> 4;
    int tt = tmp & 1;
    int b = tmp >> 1;
    int t0 = tt << 6;
    int s = b & 3;

    const float* __restrict__ W  = g_W4 + s * (16 * VP);
    const float* __restrict__ Bp = g_Bs + b * VP;

    __shared__ __align__(16) float smw[3][16 * 128];  // 3 x 8KB W chunk buffers
    __shared__ __align__(16) u64 smh[64 * 16];        // (h,h) packed per row,k
    __shared__ u64 smlz[64];                          // (-lz,-lz) packed

    int tid = threadIdx.x;

    // prefetch of one W chunk: 512 float4; each thread copies 2
    auto prefetch = [&](int ci, int buf) {
        int colbase = ((ci << 4) + vs) * 128;
        const float* src = W + colbase;
#pragma unroll
        for (int h = 0; h < 2; h++) {
            int f4 = tid + h * 256;          // 0..511
            int k = f4 >> 5;                 // 32 float4 per k-row
            int c = (f4 & 31) << 2;
            cp16(&smw[buf][k * 128 + c], src + (long)k * VP + c);
        }
        asm volatile("cp.async.commit_group;" ::: "memory");
    };

    prefetch(0, 0);
    prefetch(1, 1);

    for (int i = tid; i < 1024; i += 256)
        smh[i] = pk2(g_H[(((b << 7) + t0) << 4) + i]);
    if (PASS == 2 && tid < 64) {
        // fused Z-reduction: lz for row t0+tid of batch b
        const float* zp = g_Zpart + (long)((b << 7) + t0 + tid) * VS;
        float ssum = 0.0f;
#pragma unroll
        for (int v = 0; v < VS; v++) ssum += zp[v];
        smlz[tid] = pk2(-logf(ssum));
    }

    int warp = tid >> 5, lane = tid & 31;
    int r0 = warp << 3;                               // 8 rows per warp
    float zz[8];
#pragma unroll
    for (int r = 0; r < 8; r++) zz[r] = 0.0f;
    u64 ln2p = pk2(LN2);

    for (int ci = 0; ci < CPC; ci++) {
        int p = ci % 3;
        if (ci < CPC - 1) asm volatile("cp.async.wait_group 1;" ::: "memory");
        else              asm volatile("cp.async.wait_group 0;" ::: "memory");
        __syncthreads();   // chunk ci landed for all threads (covers smh/smlz on ci==0)

        int col = ((ci << 4) + vs) * 128 + (lane << 2);
        ulonglong2 bb = *(const ulonglong2*)(Bp + col);
        u64 a[8][2];
#pragma unroll
        for (int r = 0; r < 8; r++) { a[r][0] = bb.x; a[r][1] = bb.y; }

        const float* wp0 = &smw[p][lane << 2];
#pragma unroll
        for (int kg = 0; kg < 4; kg++) {
            const float* wp = wp0 + (kg << 9);        // kg*4 k-rows * 128
            ulonglong2 w0 = *(const ulonglong2*)(wp);
            ulonglong2 w1 = *(const ulonglong2*)(wp + 128);
            ulonglong2 w2 = *(const ulonglong2*)(wp + 256);
            ulonglong2 w3 = *(const ulonglong2*)(wp + 384);
#pragma unroll
            for (int r = 0; r < 8; r++) {
                const ulonglong2* hp = (const ulonglong2*)&smh[((r0 + r) << 4) + (kg << 2)];
                ulonglong2 h01 = hp[0];
                ulonglong2 h23 = hp[1];
                a[r][0] = f2fma(h01.x, w0.x, a[r][0]);
                a[r][1] = f2fma(h01.x, w0.y, a[r][1]);
                a[r][0] = f2fma(h01.y, w1.x, a[r][0]);
                a[r][1] = f2fma(h01.y, w1.y, a[r][1]);
                a[r][0] = f2fma(h23.x, w2.x, a[r][0]);
                a[r][1] = f2fma(h23.x, w2.y, a[r][1]);
                a[r][0] = f2fma(h23.y, w3.x, a[r][0]);
                a[r][1] = f2fma(h23.y, w3.y, a[r][1]);
            }
        }

#pragma unroll
        for (int r = 0; r < 8; r++) {
            if (PASS == 1) {
                // accumulators are log2-scaled: exp(logit+bias) = 2^acc
                float2 pp = up2(a[r][0]), qq = up2(a[r][1]);
                zz[r] += (ex2f(pp.x) + ex2f(pp.y)) + (ex2f(qq.x) + ex2f(qq.y));
            } else {
                int row = r0 + r;
                u64 lz = smlz[row];
                u64 a0 = f2fma(a[r][0], ln2p, lz);    // ln2*acc - lz
                u64 a1 = f2fma(a[r][1], ln2p, lz);
                long rowbase = (long)((t0 + row) * NB + b) * VOCAB;
                int lo = col - s;
                float2 pp = up2(a0), qq = up2(a1);
                if (lo >= 0 && lo + 4 <= VOCAB) {
                    // rowbase % 4 == s, lo % 4 == (4-s)%4 -> 16B-aligned store
                    float4 v4 = make_float4(pp.x, pp.y, qq.x, qq.y);
                    __stcs((float4*)(out + rowbase + lo), v4);
                } else {
                    float vals[4] = {pp.x, pp.y, qq.x, qq.y};
#pragma unroll
                    for (int e = 0; e < 4; e++) {
                        int v = lo + e;
                        if (v >= 0 && v < VOCAB) __stcs(out + rowbase + v, vals[e]);
                    }
                }
            }
        }

        if (ci + 2 < CPC) prefetch(ci + 2, (ci + 2) % 3);
    }

    if (PASS == 1) {
#pragma unroll
        for (int r = 0; r < 8; r++) {
            float zr = zz[r];
#pragma unroll
            for (int o = 16; o; o >>= 1) zr += __shfl_xor_sync(0xFFFFFFFFu, zr, o);
            if (lane == 0)
                g_Zpart[((b << 7) + t0 + r0 + r) * VS + vs] = zr;
        }
    }
}

// ---------------- launch ----------------
extern "C" void kernel_launch(void* const* d_in, const int* in_sizes, int n_in,
                              void* d_out, int out_size) {
    const int*   ids  = (const int*)  d_in[0];
    const float* we   = (const float*)d_in[1];
    const float* i2h  = (const float*)d_in[2];
    const float* h2o  = (const float*)d_in[3];
    const float* bias = (const float*)d_in[4];
    const float* h0f  = (const float*)d_in[5];
    const float* h0b  = (const float*)d_in[6];
    float* out = (float*)d_out;

    {
        int n = W_TOTAL + B_TOTAL;
        prep_kernel<<<(n + 255) / 256, 256>>>(h2o, bias);       // launch 0
    }
    {
        int n = NROWS * HID;
        emb_kernel<<<(n + 255) / 256, 256>>>(ids, we, i2h);     // launch 1
    }
    rnn_kernel<<<24, 128>>>(i2h, h0f, h0b);                     // launch 2

    pass_kernel<1><<<NB * 2 * VS, 256>>>(out);                  // launch 3 (ncu capture slot)
    pass_kernel<2><<<NB * 2 * VS, 256>>>(out);                  // launch 4 (lz fused in prologue)
}